// round 11
// baseline (speedup 1.0000x reference)
#include <cuda_runtime.h>
#include <math.h>
#include <stdint.h>

// DPLSTMCell row-0, R11: balanced dual-path inside every warp.
// R10 proved LDG + cp.async queues add capacity (8.93 -> 8.70us) but partitioned the
// paths by warp (each path idle half the time). R11: every warp splits its own 4KB row:
//   float4 chunks 0..3  -> cp.async.cg into smem   (async queue)
//   float4 chunks 4..7  -> front-batched LDG.128   (LDG queue, compute overlaps async)
// Fast MUFU epilogue (R7+). No .nc / evict hints (warm regressions R5/R7).

#define H 1024
#define D 1024

__device__ __forceinline__ float warp_reduce(float v) {
    #pragma unroll
    for (int off = 16; off > 0; off >>= 1)
        v += __shfl_xor_sync(0xFFFFFFFFu, v, off);
    return v;
}

__device__ __forceinline__ float fast_tanh(float x) {
    float r;
    asm("tanh.approx.f32 %0, %1;" : "=f"(r) : "f"(x));
    return r;
}
__device__ __forceinline__ float fast_sigmoid(float x) {
    return 0.5f * fast_tanh(0.5f * x) + 0.5f;
}

__global__ __launch_bounds__(256)
void lstm_row0_dual2_kernel(const float* __restrict__ x,
                            const float* __restrict__ h,
                            const float* __restrict__ c_prev,
                            const float* __restrict__ Wih,
                            const float* __restrict__ Whh,
                            const float* __restrict__ bih,
                            const float* __restrict__ bhh,
                            float* __restrict__ out) {
    __shared__ __align__(128) float4 swt[8 * 128];  // 8 rows x 128 float4 = 16KB
    __shared__ float sums[8];

    const int n    = blockIdx.x;
    const int tid  = threadIdx.x;
    const int wid  = tid >> 5;            // row: gate = wid>>1, mat = wid&1
    const int lane = tid & 31;
    const int gate = wid >> 1;
    const int mat  = wid & 1;

    const float* __restrict__ W =
        (mat ? Whh : Wih) + (size_t)(gate * H + n) * D;
    const float4* __restrict__ w4 = reinterpret_cast<const float4*>(W);
    const float4* __restrict__ v4 = reinterpret_cast<const float4*>(mat ? h : x);

    // --- async half: chunks 0..3 -> smem ---
    #pragma unroll
    for (int i = 0; i < 4; i++) {
        const int idx = lane + i * 32;                  // 0..127
        const uint32_t dst =
            (uint32_t)__cvta_generic_to_shared(&swt[wid * 128 + idx]);
        asm volatile("cp.async.cg.shared.global [%0], [%1], 16;"
                     :: "r"(dst), "l"(w4 + idx) : "memory");
    }
    asm volatile("cp.async.commit_group;" ::: "memory");

    // --- LDG half: chunks 4..7 front-batched into registers ---
    float4 wr[4];
    #pragma unroll
    for (int i = 0; i < 4; i++)
        wr[i] = w4[lane + (i + 4) * 32];

    // Vector for LDG half (L2-hot broadcast), then compute it while async is in flight.
    float acc = 0.0f;
    {
        float4 xv[4];
        #pragma unroll
        for (int i = 0; i < 4; i++)
            xv[i] = v4[lane + (i + 4) * 32];
        #pragma unroll
        for (int i = 0; i < 4; i++)
            acc += wr[i].x * xv[i].x + wr[i].y * xv[i].y
                 + wr[i].z * xv[i].z + wr[i].w * xv[i].w;
    }

    // Vector for async half.
    float4 xv0[4];
    #pragma unroll
    for (int i = 0; i < 4; i++)
        xv0[i] = v4[lane + i * 32];

    asm volatile("cp.async.wait_group 0;" ::: "memory");
    __syncwarp();

    #pragma unroll
    for (int i = 0; i < 4; i++) {
        const float4 wv = swt[wid * 128 + lane + i * 32];
        acc += wv.x * xv0[i].x + wv.y * xv0[i].y
             + wv.z * xv0[i].z + wv.w * xv0[i].w;
    }

    acc = warp_reduce(acc);
    if (lane == 0) sums[wid] = acc;
    __syncthreads();

    if (tid == 0) {
        float gi = sums[0] + sums[1] + bih[n]         + bhh[n];
        float gf = sums[2] + sums[3] + bih[H + n]     + bhh[H + n];
        float gg = sums[4] + sums[5] + bih[2 * H + n] + bhh[2 * H + n];
        float go = sums[6] + sums[7] + bih[3 * H + n] + bhh[3 * H + n];

        float i_t = fast_sigmoid(gi);
        float f_t = fast_sigmoid(gf);
        float g_t = fast_tanh(gg);
        float o_t = fast_sigmoid(go);

        float c_t = f_t * c_prev[n] + i_t * g_t;
        out[n] = o_t * fast_tanh(c_t);
    }
}

extern "C" void kernel_launch(void* const* d_in, const int* in_sizes, int n_in,
                              void* d_out, int out_size) {
    const float* x      = (const float*)d_in[0];
    const float* h      = (const float*)d_in[1];
    const float* c_prev = (const float*)d_in[2];
    const float* Wih    = (const float*)d_in[3];
    const float* Whh    = (const float*)d_in[4];
    const float* bih    = (const float*)d_in[5];
    const float* bhh    = (const float*)d_in[6];
    float* out = (float*)d_out;

    lstm_row0_dual2_kernel<<<H, 256>>>(x, h, c_prev, Wih, Whh, bih, bhh, out);
}

// round 12
// speedup vs baseline: 1.1571x; 1.1571x over previous
#include <cuda_runtime.h>
#include <math.h>
#include <stdint.h>

// DPLSTMCell row-0, R12: triple-path memory supply (extends R10, the warm-best 8.70us).
// Three independently-tracked memory engines share the weight stream per block:
//   rows 0-3 (warps 0-3): plain LDG.128          (LDG queue   - warm-fastest path)
//   rows 4-5 (warps 4-5): cp.async.cg -> smem    (LDGSTS queue)
//   rows 6-7 (warps 6-7): cp.async.bulk -> smem  (TMA queue, mbarrier completion)
// row r: gate=r>>1, mat=r&1. No warp blocks on a foreign path (R11 lesson).
// Fast MUFU epilogue (R7+). No .nc/evict hints (warm regressions R5/R7).

#define H 1024
#define D 1024

__device__ __forceinline__ float warp_reduce(float v) {
    #pragma unroll
    for (int off = 16; off > 0; off >>= 1)
        v += __shfl_xor_sync(0xFFFFFFFFu, v, off);
    return v;
}

__device__ __forceinline__ float fast_tanh(float x) {
    float r;
    asm("tanh.approx.f32 %0, %1;" : "=f"(r) : "f"(x));
    return r;
}
__device__ __forceinline__ float fast_sigmoid(float x) {
    return 0.5f * fast_tanh(0.5f * x) + 0.5f;
}

__global__ __launch_bounds__(256)
void lstm_row0_tri_kernel(const float* __restrict__ x,
                          const float* __restrict__ h,
                          const float* __restrict__ c_prev,
                          const float* __restrict__ Wih,
                          const float* __restrict__ Whh,
                          const float* __restrict__ bih,
                          const float* __restrict__ bhh,
                          float* __restrict__ out) {
    __shared__ __align__(128) float4 sasync[2 * 256];  // rows 4,5 : 8KB
    __shared__ __align__(128) float4 stma[2 * 256];    // rows 6,7 : 8KB
    __shared__ __align__(8) uint64_t mbar;
    __shared__ float sums[8];

    const int n    = blockIdx.x;
    const int tid  = threadIdx.x;
    const int wid  = tid >> 5;            // row index 0..7
    const int lane = tid & 31;
    const int gate = wid >> 1;
    const int mat  = wid & 1;

    const uint32_t mbar_a = (uint32_t)__cvta_generic_to_shared(&mbar);

    if (tid == 0)
        asm volatile("mbarrier.init.shared.b64 [%0], 1;" :: "r"(mbar_a) : "memory");
    __syncthreads();

    if (tid == 0) {
        // TMA path: rows 6 (g3,ih) and 7 (g3,hh), 4KB each.
        asm volatile("mbarrier.arrive.expect_tx.shared.b64 _, [%0], %1;"
                     :: "r"(mbar_a), "r"(2 * D * 4) : "memory");
        const float* s6 = Wih + (size_t)(3 * H + n) * D;
        const float* s7 = Whh + (size_t)(3 * H + n) * D;
        const uint32_t d6 = (uint32_t)__cvta_generic_to_shared(&stma[0]);
        const uint32_t d7 = (uint32_t)__cvta_generic_to_shared(&stma[256]);
        asm volatile("cp.async.bulk.shared::cta.global.mbarrier::complete_tx::bytes "
                     "[%0], [%1], %2, [%3];"
                     :: "r"(d6), "l"(s6), "n"(D * 4), "r"(mbar_a) : "memory");
        asm volatile("cp.async.bulk.shared::cta.global.mbarrier::complete_tx::bytes "
                     "[%0], [%1], %2, [%3];"
                     :: "r"(d7), "l"(s7), "n"(D * 4), "r"(mbar_a) : "memory");
    }

    const float4* __restrict__ v4 = reinterpret_cast<const float4*>(mat ? h : x);
    float acc = 0.0f;

    if (wid < 4) {
        // ---- LDG path (exact R1 loop) ----
        const float4* __restrict__ w4 = reinterpret_cast<const float4*>(
            (mat ? Whh : Wih) + (size_t)(gate * H + n) * D);
        #pragma unroll
        for (int i = 0; i < 8; i++) {
            const int idx = lane + i * 32;
            const float4 wv = w4[idx];
            const float4 xv = v4[idx];
            acc += wv.x * xv.x + wv.y * xv.y + wv.z * xv.z + wv.w * xv.w;
        }
    } else if (wid < 6) {
        // ---- cp.async path ----
        const int s = wid - 4;
        const float* src_base = (mat ? Whh : Wih) + (size_t)(gate * H + n) * D;
        #pragma unroll
        for (int i = 0; i < 8; i++) {
            const int idx = lane + i * 32;
            const uint32_t dst =
                (uint32_t)__cvta_generic_to_shared(&sasync[s * 256 + idx]);
            asm volatile("cp.async.cg.shared.global [%0], [%1], 16;"
                         :: "r"(dst), "l"(src_base + idx * 4) : "memory");
        }
        asm volatile("cp.async.commit_group;" ::: "memory");

        float4 vr[8];
        #pragma unroll
        for (int i = 0; i < 8; i++)
            vr[i] = v4[lane + i * 32];

        asm volatile("cp.async.wait_group 0;" ::: "memory");
        __syncwarp();

        #pragma unroll
        for (int i = 0; i < 8; i++) {
            const float4 wv = sasync[s * 256 + lane + i * 32];
            acc += wv.x * vr[i].x + wv.y * vr[i].y
                 + wv.z * vr[i].z + wv.w * vr[i].w;
        }
    } else {
        // ---- TMA path ----
        const int s = wid - 6;
        float4 vr[8];
        #pragma unroll
        for (int i = 0; i < 8; i++)
            vr[i] = v4[lane + i * 32];

        uint32_t done;
        asm volatile(
            "{\n\t.reg .pred p;\n\t"
            "mbarrier.try_wait.parity.acquire.cta.shared::cta.b64 p, [%1], 0;\n\t"
            "selp.b32 %0, 1, 0, p;\n\t}"
            : "=r"(done) : "r"(mbar_a) : "memory");
        if (!done) {
            asm volatile(
                "{\n\t.reg .pred P1;\n\t"
                "TW_%=:\n\t"
                "mbarrier.try_wait.parity.acquire.cta.shared::cta.b64 P1, [%0], 0, 0x989680;\n\t"
                "@P1 bra.uni TD_%=;\n\t"
                "bra.uni TW_%=;\n\t"
                "TD_%=:\n\t}"
                :: "r"(mbar_a) : "memory");
        }

        #pragma unroll
        for (int i = 0; i < 8; i++) {
            const float4 wv = stma[s * 256 + lane + i * 32];
            acc += wv.x * vr[i].x + wv.y * vr[i].y
                 + wv.z * vr[i].z + wv.w * vr[i].w;
        }
    }

    acc = warp_reduce(acc);
    if (lane == 0) sums[wid] = acc;
    __syncthreads();

    if (tid == 0) {
        float gi = sums[0] + sums[1] + bih[n]         + bhh[n];
        float gf = sums[2] + sums[3] + bih[H + n]     + bhh[H + n];
        float gg = sums[4] + sums[5] + bih[2 * H + n] + bhh[2 * H + n];
        float go = sums[6] + sums[7] + bih[3 * H + n] + bhh[3 * H + n];

        float i_t = fast_sigmoid(gi);
        float f_t = fast_sigmoid(gf);
        float g_t = fast_tanh(gg);
        float o_t = fast_sigmoid(go);

        float c_t = f_t * c_prev[n] + i_t * g_t;
        out[n] = o_t * fast_tanh(c_t);
    }
}

extern "C" void kernel_launch(void* const* d_in, const int* in_sizes, int n_in,
                              void* d_out, int out_size) {
    const float* x      = (const float*)d_in[0];
    const float* h      = (const float*)d_in[1];
    const float* c_prev = (const float*)d_in[2];
    const float* Wih    = (const float*)d_in[3];
    const float* Whh    = (const float*)d_in[4];
    const float* bih    = (const float*)d_in[5];
    const float* bhh    = (const float*)d_in[6];
    float* out = (float*)d_out;

    lstm_row0_tri_kernel<<<H, 256>>>(x, h, c_prev, Wih, Whh, bih, bhh, out);
}